// round 16
// baseline (speedup 1.0000x reference)
#include <cuda_runtime.h>
#include <cuda_bf16.h>
#include <cstdint>

// Problem constants
#define BB   32
#define SRC  1024
#define SEQ  128
#define CTX  5
#define DM   512
#define KPY  (CTX*DM)   // 2560

// ---------------------------------------------------------------------------
// Scratch (device globals; no allocations allowed)
// ---------------------------------------------------------------------------
__device__ __nv_bfloat16 g_xe_hi [(size_t)BB*SRC*DM];
__device__ __nv_bfloat16 g_xe_lo [(size_t)BB*SRC*DM];
__device__ __nv_bfloat16 g_yce_hi[(size_t)BB*SEQ*KPY];
__device__ __nv_bfloat16 g_pwt_hi[(size_t)DM*KPY];
__device__ __nv_bfloat16 g_py_hi [(size_t)BB*SEQ*DM];
__device__ __nv_bfloat16 g_a_hi  [(size_t)BB*SEQ*SRC];
__device__ __nv_bfloat16 g_a_lo  [(size_t)BB*SEQ*SRC];
__device__ float         g_part  [(size_t)2*BB*SEQ*DM];   // split-K partials (py)

// ---------------------------------------------------------------------------
// Helpers
// ---------------------------------------------------------------------------
__device__ __forceinline__ uint32_t smem_to_u32(const void* p) {
    uint32_t a;
    asm("{ .reg .u64 t; cvta.to.shared.u64 t, %1; cvt.u32.u64 %0, t; }"
        : "=r"(a) : "l"(p));
    return a;
}

#define CP_ASYNC16(dst, src) \
    asm volatile("cp.async.cg.shared.global [%0], [%1], 16;" \
                 :: "r"(dst), "l"(src) : "memory")
#define CP_COMMIT() asm volatile("cp.async.commit_group;" ::: "memory")
#define CP_WAIT(N)  asm volatile("cp.async.wait_group %0;" :: "n"(N) : "memory")

#define REDG_ADD_F32(addr, val) \
    asm volatile("red.global.add.f32 [%0], %1;" :: "l"(addr), "f"(val) : "memory")

__device__ __forceinline__ void ldsm_x4(uint32_t r[4], uint32_t addr) {
    asm volatile("ldmatrix.sync.aligned.m8n8.x4.shared.b16 {%0,%1,%2,%3}, [%4];"
                 : "=r"(r[0]), "=r"(r[1]), "=r"(r[2]), "=r"(r[3]) : "r"(addr));
}
__device__ __forceinline__ void ldsm_x4_trans(uint32_t r[4], uint32_t addr) {
    asm volatile("ldmatrix.sync.aligned.m8n8.x4.trans.shared.b16 {%0,%1,%2,%3}, [%4];"
                 : "=r"(r[0]), "=r"(r[1]), "=r"(r[2]), "=r"(r[3]) : "r"(addr));
}

__device__ __forceinline__ void mma16816(float c[4],
                                         uint32_t a0, uint32_t a1, uint32_t a2, uint32_t a3,
                                         uint32_t b0, uint32_t b1) {
    asm volatile("mma.sync.aligned.m16n8k16.row.col.f32.bf16.bf16.f32 "
                 "{%0,%1,%2,%3}, {%4,%5,%6,%7}, {%8,%9}, {%0,%1,%2,%3};"
                 : "+f"(c[0]), "+f"(c[1]), "+f"(c[2]), "+f"(c[3])
                 : "r"(a0), "r"(a1), "r"(a2), "r"(a3), "r"(b0), "r"(b1));
}

// fp32 -> (bf16 hi, bf16 lo) split
__device__ __forceinline__ void split2(float v, unsigned short& h, unsigned short& l) {
    __nv_bfloat16 hb = __float2bfloat16(v);
    __nv_bfloat16 lb = __float2bfloat16(v - __bfloat162float(hb));
    h = __bfloat16_as_ushort(hb);
    l = __bfloat16_as_ushort(lb);
}

// ---------------------------------------------------------------------------
// Fused prep: [0, YCE) gather+bf16 yce; [YCE, YCE+PWT) pwt transpose (hi only);
// [YCE+PWT, +ZOUT) zero-init d_out's out region (for RED accumulation).
// ---------------------------------------------------------------------------
#define YCE_BLOCKS (BB * SEQ * CTX / 4)      // 5120
#define PWT_BLOCKS ((KPY / 64) * (DM / 64))  // 320
#define ZOUT_BLOCKS ((BB * SEQ * DM) / 4096) // 512

__global__ __launch_bounds__(256)
void prep_fused(const int* __restrict__ yc, const float* __restrict__ G,
                const float* __restrict__ Pw, float* __restrict__ out_zero) {
    __shared__ float s[64][65];
    const int bid = blockIdx.x;
    const int t = threadIdx.x;

    if (bid < YCE_BLOCKS) {
        const int c = bid % CTX;
        const int m = (bid / CTX) * 4 + (t >> 6);
        const int col8 = (t & 63) * 8;
        const int tok = __ldg(&yc[m * CTX + c]);
        const float* src = G + (size_t)tok * DM + col8;
        float4 a = __ldg((const float4*)src);
        float4 b = __ldg((const float4*)(src + 4));
        float v[8] = {a.x, a.y, a.z, a.w, b.x, b.y, b.z, b.w};
        union { unsigned short us[8]; uint4 u; } H;
#pragma unroll
        for (int i = 0; i < 8; i++)
            H.us[i] = __bfloat16_as_ushort(__float2bfloat16(v[i]));
        *(uint4*)(g_yce_hi + (size_t)m * KPY + c * DM + col8) = H.u;
    } else if (bid < YCE_BLOCKS + PWT_BLOCKS) {
        const int j = bid - YCE_BLOCKS;
        const int k0 = (j % (KPY / 64)) * 64;
        const int n0 = (j / (KPY / 64)) * 64;
        const int tx = t & 31, ty = t >> 5;
#pragma unroll
        for (int i = 0; i < 8; i++) {
            const int r = ty + i * 8;
            float2 v = *(const float2*)(Pw + (size_t)(k0 + r) * DM + n0 + tx * 2);
            s[r][tx * 2] = v.x; s[r][tx * 2 + 1] = v.y;
        }
        __syncthreads();
#pragma unroll
        for (int i = 0; i < 8; i++) {
            const int nr = ty + i * 8;
            unsigned short h0 = __bfloat16_as_ushort(__float2bfloat16(s[tx * 2][nr]));
            unsigned short h1 = __bfloat16_as_ushort(__float2bfloat16(s[tx * 2 + 1][nr]));
            const size_t off = (size_t)(n0 + nr) * KPY + k0 + tx * 2;
            *(unsigned*)((unsigned short*)g_pwt_hi + off) = (unsigned)h0 | ((unsigned)h1 << 16);
        }
    } else {
        const int j = bid - YCE_BLOCKS - PWT_BLOCKS;
        float* p = out_zero + (size_t)j * 4096 + t * 16;
        const uint4 z = make_uint4(0u, 0u, 0u, 0u);
#pragma unroll
        for (int q = 0; q < 4; q++) *(uint4*)(p + q * 4) = z;
    }
}

// ---------------------------------------------------------------------------
// mma.sync GEMM.
// MODE 1: 1-term  A_hi x B_hi  (both effectively bf16)
// MODE 3: 3-term  A' = [Ahi|Ahi|Alo], B' = [Bhi|Blo|Bhi]
// NSTG: cp.async pipeline depth
// REDC=true: epilogue accumulates into C via red.global.add.f32 (C pre-zeroed)
// CTA tile 128x128, BK=32, 8 warps, m16n8k16.
// Extra z-planes (z >= zmain) run an independent xe gather+split (overlap).
// ---------------------------------------------------------------------------
#define SROW 40
#define BROW 136
#define ATILE_B (128 * SROW * 2)   // 10240
#define BTILE_NT (128 * SROW * 2)  // 10240
#define BTILE_TR (32 * BROW * 2)   // 8704

template<int K, bool TRANSB, int MODE, bool REDC, int NSTG>
__global__ __launch_bounds__(256, 2)
void mma_gemm_kernel(const __nv_bfloat16* __restrict__ Ahi, const __nv_bfloat16* __restrict__ Alo,
                     size_t strideA, int lda,
                     const __nv_bfloat16* __restrict__ Bhi, const __nv_bfloat16* __restrict__ Blo,
                     size_t strideB, int ldb,
                     float* __restrict__ C, size_t strideC, int ldc,
                     int ksplit, size_t strideS,
                     int zmain, const int* __restrict__ gx, const float* __restrict__ gF) {
    const int tid = threadIdx.x;
    const int z   = blockIdx.z;

    // ---- piggyback plane: gather + split xe (independent of GEMM inputs) ----
    if (z >= zmain) {
        const int gid  = blockIdx.y * gridDim.x + blockIdx.x;   // 0..127
        const int rsub = tid >> 6;
        const int col8 = (tid & 63) * 8;
        const int rbase = gid * 256;
#pragma unroll 4
        for (int rr = 0; rr < 64; rr++) {
            const int row = rbase + rr * 4 + rsub;
            const int tok = __ldg(&gx[row]);
            const float* src = gF + (size_t)tok * DM + col8;
            float4 a = __ldg((const float4*)src);
            float4 b = __ldg((const float4*)(src + 4));
            float v[8] = {a.x, a.y, a.z, a.w, b.x, b.y, b.z, b.w};
            union { unsigned short us[8]; uint4 u; } H, L;
#pragma unroll
            for (int i = 0; i < 8; i++) split2(v[i], H.us[i], L.us[i]);
            *(uint4*)(g_xe_hi + (size_t)row * DM + col8) = H.u;
            *(uint4*)(g_xe_lo + (size_t)row * DM + col8) = L.u;
        }
        return;
    }

    constexpr int BTILE   = TRANSB ? BTILE_TR : BTILE_NT;
    constexpr int BSLOTS  = (MODE == 1) ? 1 : 2;
    constexpr int STAGE_B = ATILE_B + BSLOTS * BTILE;
    constexpr int NC1 = K / 32;
    constexpr int NCT = (MODE == 3) ? 2 * NC1 : NC1;
    constexpr int SP  = (MODE == 3) ? (3 * NC1) / 4 : NC1 / 2;

    extern __shared__ __align__(16) unsigned char smbuf[];
    const uint32_t s_base = smem_to_u32(smbuf);
    const uint32_t sA  = s_base;
    const uint32_t sB0 = s_base + ATILE_B;

    const int lane = tid & 31;
    const int wid  = tid >> 5;
    const int wm   = wid & 1;
    const int wn   = wid >> 1;
    const int quad = lane >> 3;
    const int l8   = lane & 7;

    const int m0 = blockIdx.y * 128;
    const int n0 = blockIdx.x * 128;
    const int s_k = (ksplit == 2) ? (z & 1) : 0;
    const size_t bz = (ksplit == 2) ? (z >> 1) : z;

    const __nv_bfloat16* Ah = Ahi + bz * strideA + (size_t)m0 * lda;
    const __nv_bfloat16* Al = Alo + bz * strideA + (size_t)m0 * lda;
    const __nv_bfloat16* Bh;
    const __nv_bfloat16* Bl;
    if (TRANSB) { Bh = Bhi + bz * strideB + n0; Bl = Blo + bz * strideB + n0; }
    else        { Bh = Bhi + bz * strideB + (size_t)n0 * ldb;
                  Bl = Blo + bz * strideB + (size_t)n0 * ldb; }

    const int lrow   = tid >> 2;
    const int lchunk = tid & 3;
    const int tb_row = tid >> 4;
    const int tb_ch  = tid & 15;

    const uint32_t a_addr0 = sA + ((uint32_t)(wm * 64 + (quad & 1) * 8 + l8) * SROW
                                   + (quad >> 1) * 8) * 2;
    const uint32_t b_addr_nt = sB0 + ((uint32_t)(wn * 32 + (quad >> 1) * 8 + l8) * SROW
                                      + (quad & 1) * 8) * 2;
    const uint32_t b_addr_tr = sB0 + ((uint32_t)((quad & 1) * 8 + l8) * BROW
                                      + wn * 32 + (quad >> 1) * 8) * 2;

    float acc[4][4][4];
#pragma unroll
    for (int i = 0; i < 4; i++)
#pragma unroll
        for (int j = 0; j < 4; j++)
#pragma unroll
            for (int r = 0; r < 4; r++) acc[i][j][r] = 0.f;

    const int c0 = (s_k == 0) ? 0 : SP;
    const int c1 = (ksplit == 2) ? ((s_k == 0) ? SP : NCT) : NCT;

    auto load_tiles = [&](int stage, int c) {
        const uint32_t bo = (uint32_t)stage * STAGE_B;
        const bool pair = (MODE == 3) && (c < NC1);
        const bool useAlo = (MODE == 3) && (c >= NC1);
        const int koff = ((MODE == 3 && c >= NC1) ? c - NC1 : c) * 32;
        const __nv_bfloat16* Ap = (useAlo ? Al : Ah) + koff;
#pragma unroll
        for (int h = 0; h < 2; h++) {
            const int r = lrow + h * 64;
            CP_ASYNC16(sA + bo + ((uint32_t)r * SROW + lchunk * 8) * 2,
                       Ap + (size_t)r * lda + lchunk * 8);
        }
        if (TRANSB) {
            const __nv_bfloat16* B0p = Bh + (size_t)koff * ldb;
#pragma unroll
            for (int h = 0; h < 2; h++) {
                const int r = tb_row + h * 16;
                CP_ASYNC16(sB0 + bo + ((uint32_t)r * BROW + tb_ch * 8) * 2,
                           B0p + (size_t)r * ldb + tb_ch * 8);
            }
            if (pair) {
                const __nv_bfloat16* B1p = Bl + (size_t)koff * ldb;
#pragma unroll
                for (int h = 0; h < 2; h++) {
                    const int r = tb_row + h * 16;
                    CP_ASYNC16(sB0 + BTILE + bo + ((uint32_t)r * BROW + tb_ch * 8) * 2,
                               B1p + (size_t)r * ldb + tb_ch * 8);
                }
            }
        } else {
            const __nv_bfloat16* B0p = Bh + koff;
#pragma unroll
            for (int h = 0; h < 2; h++) {
                const int r = lrow + h * 64;
                CP_ASYNC16(sB0 + bo + ((uint32_t)r * SROW + lchunk * 8) * 2,
                           B0p + (size_t)r * ldb + lchunk * 8);
            }
            if (pair) {
                const __nv_bfloat16* B1p = Bl + koff;
#pragma unroll
                for (int h = 0; h < 2; h++) {
                    const int r = lrow + h * 64;
                    CP_ASYNC16(sB0 + BTILE + bo + ((uint32_t)r * SROW + lchunk * 8) * 2,
                               B1p + (size_t)r * ldb + lchunk * 8);
                }
            }
        }
    };

    // prologue: fill stages 0..NSTG-2
#pragma unroll
    for (int s = 0; s < NSTG - 1; s++) {
        if (c0 + s < c1) load_tiles(s, c0 + s);
        CP_COMMIT();
    }

    int st = 0;
    int ld = NSTG - 1;
    for (int c = c0; c < c1; c++) {
        CP_WAIT(NSTG - 2);
        __syncthreads();

        const uint32_t bo = (uint32_t)st * STAGE_B;
        const bool pair = (MODE == 3) && (c < NC1);
#pragma unroll
        for (int ks = 0; ks < 2; ks++) {
            uint32_t afr[4][4];
#pragma unroll
            for (int mt = 0; mt < 4; mt++)
                ldsm_x4(afr[mt], a_addr0 + bo + mt * (16 * SROW * 2) + ks * 32);
            uint32_t bfr[2][4];
            if (TRANSB) {
#pragma unroll
                for (int p = 0; p < 2; p++)
                    ldsm_x4_trans(bfr[p], b_addr_tr + bo + ks * (16 * BROW * 2) + p * 32);
            } else {
#pragma unroll
                for (int p = 0; p < 2; p++)
                    ldsm_x4(bfr[p], b_addr_nt + bo + p * (16 * SROW * 2) + ks * 32);
            }
#pragma unroll
            for (int mt = 0; mt < 4; mt++)
#pragma unroll
                for (int nt = 0; nt < 4; nt++)
                    mma16816(acc[mt][nt],
                             afr[mt][0], afr[mt][1], afr[mt][2], afr[mt][3],
                             bfr[nt >> 1][(nt & 1) * 2], bfr[nt >> 1][(nt & 1) * 2 + 1]);
            if (pair) {
                if (TRANSB) {
#pragma unroll
                    for (int p = 0; p < 2; p++)
                        ldsm_x4_trans(bfr[p], b_addr_tr + BTILE + bo + ks * (16 * BROW * 2) + p * 32);
                } else {
#pragma unroll
                    for (int p = 0; p < 2; p++)
                        ldsm_x4(bfr[p], b_addr_nt + BTILE + bo + p * (16 * SROW * 2) + ks * 32);
                }
#pragma unroll
                for (int mt = 0; mt < 4; mt++)
#pragma unroll
                    for (int nt = 0; nt < 4; nt++)
                        mma16816(acc[mt][nt],
                                 afr[mt][0], afr[mt][1], afr[mt][2], afr[mt][3],
                                 bfr[nt >> 1][(nt & 1) * 2], bfr[nt >> 1][(nt & 1) * 2 + 1]);
            }
        }

        const int nxt = c + NSTG - 1;
        if (nxt < c1) load_tiles(ld, nxt);
        CP_COMMIT();
        st = (st == NSTG - 1) ? 0 : st + 1;
        ld = (ld == NSTG - 1) ? 0 : ld + 1;
    }

    // epilogue
    float* Cb = C + (size_t)s_k * strideS + bz * strideC;
    const int mb = m0 + wm * 64;
    const int nb = n0 + wn * 32;
#pragma unroll
    for (int mt = 0; mt < 4; mt++) {
#pragma unroll
        for (int nt = 0; nt < 4; nt++) {
            const int r  = mb + mt * 16 + (lane >> 2);
            const int cc = nb + nt * 8 + (lane & 3) * 2;
            if (REDC) {
                float* p0 = &Cb[(size_t)r * ldc + cc];
                float* p1 = &Cb[(size_t)(r + 8) * ldc + cc];
                REDG_ADD_F32(p0,     acc[mt][nt][0]);
                REDG_ADD_F32(p0 + 1, acc[mt][nt][1]);
                REDG_ADD_F32(p1,     acc[mt][nt][2]);
                REDG_ADD_F32(p1 + 1, acc[mt][nt][3]);
            } else {
                *(float2*)&Cb[(size_t)r * ldc + cc] =
                    make_float2(acc[mt][nt][0], acc[mt][nt][1]);
                *(float2*)&Cb[(size_t)(r + 8) * ldc + cc] =
                    make_float2(acc[mt][nt][2], acc[mt][nt][3]);
            }
        }
    }
}

// ---------------------------------------------------------------------------
// Split-K reduce for py: py = part0 + part1 + bias -> bf16 hi only
// ---------------------------------------------------------------------------
__global__ __launch_bounds__(256)
void reduce_bias_split_py(const float* __restrict__ Pb) {
    const size_t base = ((size_t)blockIdx.x * 256 + threadIdx.x) * 16;
    const float* p0 = g_part + base;
    const float* p1 = p0 + (size_t)BB * SEQ * DM;
    const int nb = (int)(base & (DM - 1));
    float4 a[4], b[4], c[4];
#pragma unroll
    for (int i = 0; i < 4; i++) a[i] = *(const float4*)(p0 + i * 4);
#pragma unroll
    for (int i = 0; i < 4; i++) b[i] = *(const float4*)(p1 + i * 4);
#pragma unroll
    for (int i = 0; i < 4; i++) c[i] = __ldg((const float4*)(Pb + nb + i * 4));
#pragma unroll
    for (int i = 0; i < 2; i++) {
        union { unsigned short us[8]; uint4 u; } H;
#pragma unroll
        for (int q = 0; q < 2; q++) {
            const int k = i * 2 + q;
            H.us[q*4+0] = __bfloat16_as_ushort(__float2bfloat16(a[k].x + b[k].x + c[k].x));
            H.us[q*4+1] = __bfloat16_as_ushort(__float2bfloat16(a[k].y + b[k].y + c[k].y));
            H.us[q*4+2] = __bfloat16_as_ushort(__float2bfloat16(a[k].z + b[k].z + c[k].z));
            H.us[q*4+3] = __bfloat16_as_ushort(__float2bfloat16(a[k].w + b[k].w + c[k].w));
        }
        *(uint4*)(g_py_hi + base + i * 8) = H.u;
    }
}

// ---------------------------------------------------------------------------
// Masked softmax in-place + fused bf16 hi/lo split (shuffle reductions)
// ---------------------------------------------------------------------------
__global__ __launch_bounds__(256)
void softmax_mask_split(float* __restrict__ a,
                        const int* __restrict__ x) {
    const int row = blockIdx.x;
    const int b = row >> 7;
    float* p = a + (size_t)row * SRC;
    const int* xb = x + b * SRC;
    const int t = threadIdx.x;
    const int lane = t & 31, wid = t >> 5;

    float v[4];
    float mx = -1e30f;
#pragma unroll
    for (int i = 0; i < 4; i++) {
        const int col = t + i * 256;
        float val = p[col];
        if (__ldg(&xb[col]) == 0) val -= 1e9f;
        v[i] = val;
        mx = fmaxf(mx, val);
    }
    __shared__ float wred[16];
#pragma unroll
    for (int off = 16; off > 0; off >>= 1)
        mx = fmaxf(mx, __shfl_xor_sync(0xffffffffu, mx, off));
    if (lane == 0) wred[wid] = mx;
    __syncthreads();
    mx = wred[0];
#pragma unroll
    for (int w = 1; w < 8; w++) mx = fmaxf(mx, wred[w]);

    float sum = 0.f;
#pragma unroll
    for (int i = 0; i < 4; i++) { v[i] = __expf(v[i] - mx); sum += v[i]; }
#pragma unroll
    for (int off = 16; off > 0; off >>= 1)
        sum += __shfl_xor_sync(0xffffffffu, sum, off);
    if (lane == 0) wred[8 + wid] = sum;
    __syncthreads();
    sum = wred[8];
#pragma unroll
    for (int w = 1; w < 8; w++) sum += wred[8 + w];

    const float inv = 1.0f / sum;
    unsigned short* ah = (unsigned short*)g_a_hi + (size_t)row * SRC;
    unsigned short* al = (unsigned short*)g_a_lo + (size_t)row * SRC;
#pragma unroll
    for (int i = 0; i < 4; i++) {
        const int col = t + i * 256;
        const float val = v[i] * inv;
        p[col] = val;
        unsigned short h, l;
        split2(val, h, l);
        ah[col] = h; al[col] = l;
    }
}

// ---------------------------------------------------------------------------
extern "C" void kernel_launch(void* const* d_in, const int* in_sizes, int n_in,
                              void* d_out, int out_size) {
    const int*   x   = (const int*)  d_in[0];   // [32, 1024]
    const int*   yc  = (const int*)  d_in[1];   // [32, 640]
    const float* F   = (const float*)d_in[2];   // [32000, 512]
    const float* G   = (const float*)d_in[3];   // [32000, 512]
    const float* Pw  = (const float*)d_in[4];   // [2560, 512]
    const float* Pb  = (const float*)d_in[5];   // [512]

    float* out   = (float*)d_out;                       // [32,128,512]
    float* a_out = out + (size_t)BB * SEQ * DM;         // [32,128,1024]

    constexpr int SMEM_NT1 = 5 * (ATILE_B + BTILE_NT);      // 102400 (1-term, 5 stages)
    constexpr int SMEM_TR3 = 4 * (ATILE_B + 2 * BTILE_TR);  // 110592 (3-term, 4 stages)
    cudaFuncSetAttribute(mma_gemm_kernel<KPY, false, 1, false, 5>,
                         cudaFuncAttributeMaxDynamicSharedMemorySize, SMEM_NT1);
    cudaFuncSetAttribute(mma_gemm_kernel<DM, false, 1, false, 5>,
                         cudaFuncAttributeMaxDynamicSharedMemorySize, SMEM_NT1);
    cudaFuncSetAttribute(mma_gemm_kernel<SRC, true, 3, true, 4>,
                         cudaFuncAttributeMaxDynamicSharedMemorySize, SMEM_TR3);

    __nv_bfloat16 *xe_hi, *xe_lo, *yce_hi, *pwt_hi, *py_hi, *a_hi, *a_lo;
    float* part;
    cudaGetSymbolAddress((void**)&xe_hi,  g_xe_hi);
    cudaGetSymbolAddress((void**)&xe_lo,  g_xe_lo);
    cudaGetSymbolAddress((void**)&yce_hi, g_yce_hi);
    cudaGetSymbolAddress((void**)&pwt_hi, g_pwt_hi);
    cudaGetSymbolAddress((void**)&py_hi,  g_py_hi);
    cudaGetSymbolAddress((void**)&a_hi,   g_a_hi);
    cudaGetSymbolAddress((void**)&a_lo,   g_a_lo);
    cudaGetSymbolAddress((void**)&part,   g_part);

    const size_t PART_S = (size_t)BB * SEQ * DM;

    // 1) fused: gather+bf16 yce, transpose+bf16 P_w, zero-init out region
    prep_fused<<<YCE_BLOCKS + PWT_BLOCKS + ZOUT_BLOCKS, 256>>>(yc, G, Pw, out);
    // 2) py partials (1-term, 5-stage, split-K=2) + piggybacked xe gather on z==2
    mma_gemm_kernel<KPY, false, 1, false, 5><<<dim3(DM / 128, (BB * SEQ) / 128, 3), 256, SMEM_NT1>>>(
        yce_hi, yce_hi, 0, KPY,
        pwt_hi, pwt_hi, 0, KPY,
        part, 0, DM, 2, PART_S, 2, x, F);
    // 3) reduce + bias -> py bf16
    reduce_bias_split_py<<<(BB * SEQ * DM) / (256 * 16), 256>>>(Pb);
    // 4) logits (1-term, 5-stage): a[b,s,x] = py[b,s,:] . xe[b,x,:]
    mma_gemm_kernel<DM, false, 1, false, 5><<<dim3(SRC / 128, 1, BB), 256, SMEM_NT1>>>(
        py_hi, py_hi, (size_t)SEQ * DM, DM,
        xe_hi, xe_hi, (size_t)SRC * DM, DM,
        a_out, (size_t)SEQ * SRC, SRC, 1, 0, BB, nullptr, nullptr);
    // 5) masked softmax + split
    softmax_mask_split<<<BB * SEQ, 256>>>(a_out, x);
    // 6) out (3-term, 4-stage, split-K=2 via RED, trans-B): M=128, N=512, K=1024
    mma_gemm_kernel<SRC, true, 3, true, 4><<<dim3(DM / 128, 1, BB * 2), 256, SMEM_TR3>>>(
        a_hi, a_lo, (size_t)SEQ * SRC, SRC,
        xe_hi, xe_lo, (size_t)SRC * DM, DM,
        out, (size_t)SEQ * DM, DM, 2, 0, BB * 2, nullptr, nullptr);
}

// round 17
// speedup vs baseline: 1.0625x; 1.0625x over previous
#include <cuda_runtime.h>
#include <cuda_bf16.h>
#include <cstdint>

// Problem constants
#define BB   32
#define SRC  1024
#define SEQ  128
#define CTX  5
#define DM   512
#define KPY  (CTX*DM)   // 2560

// ---------------------------------------------------------------------------
// Scratch (device globals; no allocations allowed)
// ---------------------------------------------------------------------------
__device__ __nv_bfloat16 g_xe_hi [(size_t)BB*SRC*DM];
__device__ __nv_bfloat16 g_xe_lo [(size_t)BB*SRC*DM];
__device__ __nv_bfloat16 g_yce_hi[(size_t)BB*SEQ*KPY];
__device__ __nv_bfloat16 g_pwt_hi[(size_t)DM*KPY];
__device__ __nv_bfloat16 g_py_hi [(size_t)BB*SEQ*DM];
__device__ __nv_bfloat16 g_a_hi  [(size_t)BB*SEQ*SRC];
__device__ __nv_bfloat16 g_a_lo  [(size_t)BB*SEQ*SRC];
__device__ float         g_part  [(size_t)2*BB*SEQ*DM];   // split-K partials (py)

// ---------------------------------------------------------------------------
// Helpers
// ---------------------------------------------------------------------------
__device__ __forceinline__ uint32_t smem_to_u32(const void* p) {
    uint32_t a;
    asm("{ .reg .u64 t; cvta.to.shared.u64 t, %1; cvt.u32.u64 %0, t; }"
        : "=r"(a) : "l"(p));
    return a;
}

#define CP_ASYNC16(dst, src) \
    asm volatile("cp.async.cg.shared.global [%0], [%1], 16;" \
                 :: "r"(dst), "l"(src) : "memory")
#define CP_COMMIT() asm volatile("cp.async.commit_group;" ::: "memory")
#define CP_WAIT(N)  asm volatile("cp.async.wait_group %0;" :: "n"(N) : "memory")

#define REDG_ADD_F32(addr, val) \
    asm volatile("red.global.add.f32 [%0], %1;" :: "l"(addr), "f"(val) : "memory")

__device__ __forceinline__ void ldsm_x4(uint32_t r[4], uint32_t addr) {
    asm volatile("ldmatrix.sync.aligned.m8n8.x4.shared.b16 {%0,%1,%2,%3}, [%4];"
                 : "=r"(r[0]), "=r"(r[1]), "=r"(r[2]), "=r"(r[3]) : "r"(addr));
}
__device__ __forceinline__ void ldsm_x4_trans(uint32_t r[4], uint32_t addr) {
    asm volatile("ldmatrix.sync.aligned.m8n8.x4.trans.shared.b16 {%0,%1,%2,%3}, [%4];"
                 : "=r"(r[0]), "=r"(r[1]), "=r"(r[2]), "=r"(r[3]) : "r"(addr));
}

__device__ __forceinline__ void mma16816(float c[4],
                                         uint32_t a0, uint32_t a1, uint32_t a2, uint32_t a3,
                                         uint32_t b0, uint32_t b1) {
    asm volatile("mma.sync.aligned.m16n8k16.row.col.f32.bf16.bf16.f32 "
                 "{%0,%1,%2,%3}, {%4,%5,%6,%7}, {%8,%9}, {%0,%1,%2,%3};"
                 : "+f"(c[0]), "+f"(c[1]), "+f"(c[2]), "+f"(c[3])
                 : "r"(a0), "r"(a1), "r"(a2), "r"(a3), "r"(b0), "r"(b1));
}

// fp32 -> (bf16 hi, bf16 lo) split
__device__ __forceinline__ void split2(float v, unsigned short& h, unsigned short& l) {
    __nv_bfloat16 hb = __float2bfloat16(v);
    __nv_bfloat16 lb = __float2bfloat16(v - __bfloat162float(hb));
    h = __bfloat16_as_ushort(hb);
    l = __bfloat16_as_ushort(lb);
}

// ---------------------------------------------------------------------------
// Fused prep: [0, YCE) gather+bf16 yce; [YCE, YCE+PWT) pwt transpose (hi only);
// [YCE+PWT, +ZOUT) zero-init d_out's out region (for RED accumulation).
// ---------------------------------------------------------------------------
#define YCE_BLOCKS (BB * SEQ * CTX / 4)      // 5120
#define PWT_BLOCKS ((KPY / 64) * (DM / 64))  // 320
#define ZOUT_BLOCKS ((BB * SEQ * DM) / 4096) // 512

__global__ __launch_bounds__(256)
void prep_fused(const int* __restrict__ yc, const float* __restrict__ G,
                const float* __restrict__ Pw, float* __restrict__ out_zero) {
    __shared__ float s[64][65];
    const int bid = blockIdx.x;
    const int t = threadIdx.x;

    if (bid < YCE_BLOCKS) {
        const int c = bid % CTX;
        const int m = (bid / CTX) * 4 + (t >> 6);
        const int col8 = (t & 63) * 8;
        const int tok = __ldg(&yc[m * CTX + c]);
        const float* src = G + (size_t)tok * DM + col8;
        float4 a = __ldg((const float4*)src);
        float4 b = __ldg((const float4*)(src + 4));
        float v[8] = {a.x, a.y, a.z, a.w, b.x, b.y, b.z, b.w};
        union { unsigned short us[8]; uint4 u; } H;
#pragma unroll
        for (int i = 0; i < 8; i++)
            H.us[i] = __bfloat16_as_ushort(__float2bfloat16(v[i]));
        *(uint4*)(g_yce_hi + (size_t)m * KPY + c * DM + col8) = H.u;
    } else if (bid < YCE_BLOCKS + PWT_BLOCKS) {
        const int j = bid - YCE_BLOCKS;
        const int k0 = (j % (KPY / 64)) * 64;
        const int n0 = (j / (KPY / 64)) * 64;
        const int tx = t & 31, ty = t >> 5;
#pragma unroll
        for (int i = 0; i < 8; i++) {
            const int r = ty + i * 8;
            float2 v = *(const float2*)(Pw + (size_t)(k0 + r) * DM + n0 + tx * 2);
            s[r][tx * 2] = v.x; s[r][tx * 2 + 1] = v.y;
        }
        __syncthreads();
#pragma unroll
        for (int i = 0; i < 8; i++) {
            const int nr = ty + i * 8;
            unsigned short h0 = __bfloat16_as_ushort(__float2bfloat16(s[tx * 2][nr]));
            unsigned short h1 = __bfloat16_as_ushort(__float2bfloat16(s[tx * 2 + 1][nr]));
            const size_t off = (size_t)(n0 + nr) * KPY + k0 + tx * 2;
            *(unsigned*)((unsigned short*)g_pwt_hi + off) = (unsigned)h0 | ((unsigned)h1 << 16);
        }
    } else {
        const int j = bid - YCE_BLOCKS - PWT_BLOCKS;
        float* p = out_zero + (size_t)j * 4096 + t * 16;
        const uint4 z = make_uint4(0u, 0u, 0u, 0u);
#pragma unroll
        for (int q = 0; q < 4; q++) *(uint4*)(p + q * 4) = z;
    }
}

// ---------------------------------------------------------------------------
// mma.sync GEMM.
// MODE 1: 1-term  A_hi x B_hi  (both effectively bf16)
// MODE 3: 3-term  A' = [Ahi|Ahi|Alo], B' = [Bhi|Blo|Bhi]
// NSTG: cp.async pipeline depth
// REDC=true: epilogue accumulates into C via red.global.add.f32 (C pre-zeroed)
// CTA tile 128x128, BK=32, 8 warps, m16n8k16.
// Extra z-planes (z >= zmain) run an independent xe gather+split (overlap),
// 128 rows per block across (gridDim.z - zmain) planes.
// ---------------------------------------------------------------------------
#define SROW 40
#define BROW 136
#define ATILE_B (128 * SROW * 2)   // 10240
#define BTILE_NT (128 * SROW * 2)  // 10240
#define BTILE_TR (32 * BROW * 2)   // 8704

template<int K, bool TRANSB, int MODE, bool REDC, int NSTG>
__global__ __launch_bounds__(256, 2)
void mma_gemm_kernel(const __nv_bfloat16* __restrict__ Ahi, const __nv_bfloat16* __restrict__ Alo,
                     size_t strideA, int lda,
                     const __nv_bfloat16* __restrict__ Bhi, const __nv_bfloat16* __restrict__ Blo,
                     size_t strideB, int ldb,
                     float* __restrict__ C, size_t strideC, int ldc,
                     int ksplit, size_t strideS,
                     int zmain, const int* __restrict__ gx, const float* __restrict__ gF) {
    const int tid = threadIdx.x;
    const int z   = blockIdx.z;

    // ---- piggyback planes: gather + split xe (128 rows per block) ----
    if (z >= zmain) {
        const int gid = (z - zmain) * (gridDim.x * gridDim.y)
                      + blockIdx.y * gridDim.x + blockIdx.x;      // 0..255
        const int rsub = tid >> 6;
        const int col8 = (tid & 63) * 8;
        const int rbase = gid * 128;
#pragma unroll 4
        for (int rr = 0; rr < 32; rr++) {
            const int row = rbase + rr * 4 + rsub;
            const int tok = __ldg(&gx[row]);
            const float* src = gF + (size_t)tok * DM + col8;
            float4 a = __ldg((const float4*)src);
            float4 b = __ldg((const float4*)(src + 4));
            float v[8] = {a.x, a.y, a.z, a.w, b.x, b.y, b.z, b.w};
            union { unsigned short us[8]; uint4 u; } H, L;
#pragma unroll
            for (int i = 0; i < 8; i++) split2(v[i], H.us[i], L.us[i]);
            *(uint4*)(g_xe_hi + (size_t)row * DM + col8) = H.u;
            *(uint4*)(g_xe_lo + (size_t)row * DM + col8) = L.u;
        }
        return;
    }

    constexpr int BTILE   = TRANSB ? BTILE_TR : BTILE_NT;
    constexpr int BSLOTS  = (MODE == 1) ? 1 : 2;
    constexpr int STAGE_B = ATILE_B + BSLOTS * BTILE;
    constexpr int NC1 = K / 32;
    constexpr int NCT = (MODE == 3) ? 2 * NC1 : NC1;
    constexpr int SP  = (MODE == 3) ? (3 * NC1) / 4 : NC1 / 2;

    extern __shared__ __align__(16) unsigned char smbuf[];
    const uint32_t s_base = smem_to_u32(smbuf);
    const uint32_t sA  = s_base;
    const uint32_t sB0 = s_base + ATILE_B;

    const int lane = tid & 31;
    const int wid  = tid >> 5;
    const int wm   = wid & 1;
    const int wn   = wid >> 1;
    const int quad = lane >> 3;
    const int l8   = lane & 7;

    const int m0 = blockIdx.y * 128;
    const int n0 = blockIdx.x * 128;
    const int s_k = (ksplit == 2) ? (z & 1) : 0;
    const size_t bz = (ksplit == 2) ? (z >> 1) : z;

    const __nv_bfloat16* Ah = Ahi + bz * strideA + (size_t)m0 * lda;
    const __nv_bfloat16* Al = Alo + bz * strideA + (size_t)m0 * lda;
    const __nv_bfloat16* Bh;
    const __nv_bfloat16* Bl;
    if (TRANSB) { Bh = Bhi + bz * strideB + n0; Bl = Blo + bz * strideB + n0; }
    else        { Bh = Bhi + bz * strideB + (size_t)n0 * ldb;
                  Bl = Blo + bz * strideB + (size_t)n0 * ldb; }

    const int lrow   = tid >> 2;
    const int lchunk = tid & 3;
    const int tb_row = tid >> 4;
    const int tb_ch  = tid & 15;

    const uint32_t a_addr0 = sA + ((uint32_t)(wm * 64 + (quad & 1) * 8 + l8) * SROW
                                   + (quad >> 1) * 8) * 2;
    const uint32_t b_addr_nt = sB0 + ((uint32_t)(wn * 32 + (quad >> 1) * 8 + l8) * SROW
                                      + (quad & 1) * 8) * 2;
    const uint32_t b_addr_tr = sB0 + ((uint32_t)((quad & 1) * 8 + l8) * BROW
                                      + wn * 32 + (quad >> 1) * 8) * 2;

    float acc[4][4][4];
#pragma unroll
    for (int i = 0; i < 4; i++)
#pragma unroll
        for (int j = 0; j < 4; j++)
#pragma unroll
            for (int r = 0; r < 4; r++) acc[i][j][r] = 0.f;

    const int c0 = (s_k == 0) ? 0 : SP;
    const int c1 = (ksplit == 2) ? ((s_k == 0) ? SP : NCT) : NCT;

    auto load_tiles = [&](int stage, int c) {
        const uint32_t bo = (uint32_t)stage * STAGE_B;
        const bool pair = (MODE == 3) && (c < NC1);
        const bool useAlo = (MODE == 3) && (c >= NC1);
        const int koff = ((MODE == 3 && c >= NC1) ? c - NC1 : c) * 32;
        const __nv_bfloat16* Ap = (useAlo ? Al : Ah) + koff;
#pragma unroll
        for (int h = 0; h < 2; h++) {
            const int r = lrow + h * 64;
            CP_ASYNC16(sA + bo + ((uint32_t)r * SROW + lchunk * 8) * 2,
                       Ap + (size_t)r * lda + lchunk * 8);
        }
        if (TRANSB) {
            const __nv_bfloat16* B0p = Bh + (size_t)koff * ldb;
#pragma unroll
            for (int h = 0; h < 2; h++) {
                const int r = tb_row + h * 16;
                CP_ASYNC16(sB0 + bo + ((uint32_t)r * BROW + tb_ch * 8) * 2,
                           B0p + (size_t)r * ldb + tb_ch * 8);
            }
            if (pair) {
                const __nv_bfloat16* B1p = Bl + (size_t)koff * ldb;
#pragma unroll
                for (int h = 0; h < 2; h++) {
                    const int r = tb_row + h * 16;
                    CP_ASYNC16(sB0 + BTILE + bo + ((uint32_t)r * BROW + tb_ch * 8) * 2,
                               B1p + (size_t)r * ldb + tb_ch * 8);
                }
            }
        } else {
            const __nv_bfloat16* B0p = Bh + koff;
#pragma unroll
            for (int h = 0; h < 2; h++) {
                const int r = lrow + h * 64;
                CP_ASYNC16(sB0 + bo + ((uint32_t)r * SROW + lchunk * 8) * 2,
                           B0p + (size_t)r * ldb + lchunk * 8);
            }
            if (pair) {
                const __nv_bfloat16* B1p = Bl + koff;
#pragma unroll
                for (int h = 0; h < 2; h++) {
                    const int r = lrow + h * 64;
                    CP_ASYNC16(sB0 + BTILE + bo + ((uint32_t)r * SROW + lchunk * 8) * 2,
                               B1p + (size_t)r * ldb + lchunk * 8);
                }
            }
        }
    };

    // prologue: fill stages 0..NSTG-2
#pragma unroll
    for (int s = 0; s < NSTG - 1; s++) {
        if (c0 + s < c1) load_tiles(s, c0 + s);
        CP_COMMIT();
    }

    int st = 0;
    int ld = NSTG - 1;
    for (int c = c0; c < c1; c++) {
        CP_WAIT(NSTG - 2);
        __syncthreads();

        const uint32_t bo = (uint32_t)st * STAGE_B;
        const bool pair = (MODE == 3) && (c < NC1);
#pragma unroll
        for (int ks = 0; ks < 2; ks++) {
            uint32_t afr[4][4];
#pragma unroll
            for (int mt = 0; mt < 4; mt++)
                ldsm_x4(afr[mt], a_addr0 + bo + mt * (16 * SROW * 2) + ks * 32);
            uint32_t bfr[2][4];
            if (TRANSB) {
#pragma unroll
                for (int p = 0; p < 2; p++)
                    ldsm_x4_trans(bfr[p], b_addr_tr + bo + ks * (16 * BROW * 2) + p * 32);
            } else {
#pragma unroll
                for (int p = 0; p < 2; p++)
                    ldsm_x4(bfr[p], b_addr_nt + bo + p * (16 * SROW * 2) + ks * 32);
            }
#pragma unroll
            for (int mt = 0; mt < 4; mt++)
#pragma unroll
                for (int nt = 0; nt < 4; nt++)
                    mma16816(acc[mt][nt],
                             afr[mt][0], afr[mt][1], afr[mt][2], afr[mt][3],
                             bfr[nt >> 1][(nt & 1) * 2], bfr[nt >> 1][(nt & 1) * 2 + 1]);
            if (pair) {
                if (TRANSB) {
#pragma unroll
                    for (int p = 0; p < 2; p++)
                        ldsm_x4_trans(bfr[p], b_addr_tr + BTILE + bo + ks * (16 * BROW * 2) + p * 32);
                } else {
#pragma unroll
                    for (int p = 0; p < 2; p++)
                        ldsm_x4(bfr[p], b_addr_nt + BTILE + bo + p * (16 * SROW * 2) + ks * 32);
                }
#pragma unroll
                for (int mt = 0; mt < 4; mt++)
#pragma unroll
                    for (int nt = 0; nt < 4; nt++)
                        mma16816(acc[mt][nt],
                                 afr[mt][0], afr[mt][1], afr[mt][2], afr[mt][3],
                                 bfr[nt >> 1][(nt & 1) * 2], bfr[nt >> 1][(nt & 1) * 2 + 1]);
            }
        }

        const int nxt = c + NSTG - 1;
        if (nxt < c1) load_tiles(ld, nxt);
        CP_COMMIT();
        st = (st == NSTG - 1) ? 0 : st + 1;
        ld = (ld == NSTG - 1) ? 0 : ld + 1;
    }

    // epilogue
    float* Cb = C + (size_t)s_k * strideS + bz * strideC;
    const int mb = m0 + wm * 64;
    const int nb = n0 + wn * 32;
#pragma unroll
    for (int mt = 0; mt < 4; mt++) {
#pragma unroll
        for (int nt = 0; nt < 4; nt++) {
            const int r  = mb + mt * 16 + (lane >> 2);
            const int cc = nb + nt * 8 + (lane & 3) * 2;
            if (REDC) {
                float* p0 = &Cb[(size_t)r * ldc + cc];
                float* p1 = &Cb[(size_t)(r + 8) * ldc + cc];
                REDG_ADD_F32(p0,     acc[mt][nt][0]);
                REDG_ADD_F32(p0 + 1, acc[mt][nt][1]);
                REDG_ADD_F32(p1,     acc[mt][nt][2]);
                REDG_ADD_F32(p1 + 1, acc[mt][nt][3]);
            } else {
                *(float2*)&Cb[(size_t)r * ldc + cc] =
                    make_float2(acc[mt][nt][0], acc[mt][nt][1]);
                *(float2*)&Cb[(size_t)(r + 8) * ldc + cc] =
                    make_float2(acc[mt][nt][2], acc[mt][nt][3]);
            }
        }
    }
}

// ---------------------------------------------------------------------------
// Split-K reduce for py: py = part0 + part1 + bias -> bf16 hi only
// ---------------------------------------------------------------------------
__global__ __launch_bounds__(256)
void reduce_bias_split_py(const float* __restrict__ Pb) {
    const size_t base = ((size_t)blockIdx.x * 256 + threadIdx.x) * 16;
    const float* p0 = g_part + base;
    const float* p1 = p0 + (size_t)BB * SEQ * DM;
    const int nb = (int)(base & (DM - 1));
    float4 a[4], b[4], c[4];
#pragma unroll
    for (int i = 0; i < 4; i++) a[i] = *(const float4*)(p0 + i * 4);
#pragma unroll
    for (int i = 0; i < 4; i++) b[i] = *(const float4*)(p1 + i * 4);
#pragma unroll
    for (int i = 0; i < 4; i++) c[i] = __ldg((const float4*)(Pb + nb + i * 4));
#pragma unroll
    for (int i = 0; i < 2; i++) {
        union { unsigned short us[8]; uint4 u; } H;
#pragma unroll
        for (int q = 0; q < 2; q++) {
            const int k = i * 2 + q;
            H.us[q*4+0] = __bfloat16_as_ushort(__float2bfloat16(a[k].x + b[k].x + c[k].x));
            H.us[q*4+1] = __bfloat16_as_ushort(__float2bfloat16(a[k].y + b[k].y + c[k].y));
            H.us[q*4+2] = __bfloat16_as_ushort(__float2bfloat16(a[k].z + b[k].z + c[k].z));
            H.us[q*4+3] = __bfloat16_as_ushort(__float2bfloat16(a[k].w + b[k].w + c[k].w));
        }
        *(uint4*)(g_py_hi + base + i * 8) = H.u;
    }
}

// ---------------------------------------------------------------------------
// Masked softmax in-place + fused bf16 hi/lo split (shuffle reductions)
// ---------------------------------------------------------------------------
__global__ __launch_bounds__(256)
void softmax_mask_split(float* __restrict__ a,
                        const int* __restrict__ x) {
    const int row = blockIdx.x;
    const int b = row >> 7;
    float* p = a + (size_t)row * SRC;
    const int* xb = x + b * SRC;
    const int t = threadIdx.x;
    const int lane = t & 31, wid = t >> 5;

    float v[4];
    float mx = -1e30f;
#pragma unroll
    for (int i = 0; i < 4; i++) {
        const int col = t + i * 256;
        float val = p[col];
        if (__ldg(&xb[col]) == 0) val -= 1e9f;
        v[i] = val;
        mx = fmaxf(mx, val);
    }
    __shared__ float wred[16];
#pragma unroll
    for (int off = 16; off > 0; off >>= 1)
        mx = fmaxf(mx, __shfl_xor_sync(0xffffffffu, mx, off));
    if (lane == 0) wred[wid] = mx;
    __syncthreads();
    mx = wred[0];
#pragma unroll
    for (int w = 1; w < 8; w++) mx = fmaxf(mx, wred[w]);

    float sum = 0.f;
#pragma unroll
    for (int i = 0; i < 4; i++) { v[i] = __expf(v[i] - mx); sum += v[i]; }
#pragma unroll
    for (int off = 16; off > 0; off >>= 1)
        sum += __shfl_xor_sync(0xffffffffu, sum, off);
    if (lane == 0) wred[8 + wid] = sum;
    __syncthreads();
    sum = wred[8];
#pragma unroll
    for (int w = 1; w < 8; w++) sum += wred[8 + w];

    const float inv = 1.0f / sum;
    unsigned short* ah = (unsigned short*)g_a_hi + (size_t)row * SRC;
    unsigned short* al = (unsigned short*)g_a_lo + (size_t)row * SRC;
#pragma unroll
    for (int i = 0; i < 4; i++) {
        const int col = t + i * 256;
        const float val = v[i] * inv;
        p[col] = val;
        unsigned short h, l;
        split2(val, h, l);
        ah[col] = h; al[col] = l;
    }
}

// ---------------------------------------------------------------------------
extern "C" void kernel_launch(void* const* d_in, const int* in_sizes, int n_in,
                              void* d_out, int out_size) {
    const int*   x   = (const int*)  d_in[0];   // [32, 1024]
    const int*   yc  = (const int*)  d_in[1];   // [32, 640]
    const float* F   = (const float*)d_in[2];   // [32000, 512]
    const float* G   = (const float*)d_in[3];   // [32000, 512]
    const float* Pw  = (const float*)d_in[4];   // [2560, 512]
    const float* Pb  = (const float*)d_in[5];   // [512]

    float* out   = (float*)d_out;                       // [32,128,512]
    float* a_out = out + (size_t)BB * SEQ * DM;         // [32,128,1024]

    constexpr int SMEM_NT1 = 4 * (ATILE_B + BTILE_NT);      // 81920 (1-term, 4 stages)
    constexpr int SMEM_TR3 = 3 * (ATILE_B + 2 * BTILE_TR);  // 82944 (3-term, 3 stages)
    cudaFuncSetAttribute(mma_gemm_kernel<KPY, false, 1, false, 4>,
                         cudaFuncAttributeMaxDynamicSharedMemorySize, SMEM_NT1);
    cudaFuncSetAttribute(mma_gemm_kernel<DM, false, 1, false, 4>,
                         cudaFuncAttributeMaxDynamicSharedMemorySize, SMEM_NT1);
    cudaFuncSetAttribute(mma_gemm_kernel<SRC, true, 3, true, 3>,
                         cudaFuncAttributeMaxDynamicSharedMemorySize, SMEM_TR3);

    __nv_bfloat16 *xe_hi, *xe_lo, *yce_hi, *pwt_hi, *py_hi, *a_hi, *a_lo;
    float* part;
    cudaGetSymbolAddress((void**)&xe_hi,  g_xe_hi);
    cudaGetSymbolAddress((void**)&xe_lo,  g_xe_lo);
    cudaGetSymbolAddress((void**)&yce_hi, g_yce_hi);
    cudaGetSymbolAddress((void**)&pwt_hi, g_pwt_hi);
    cudaGetSymbolAddress((void**)&py_hi,  g_py_hi);
    cudaGetSymbolAddress((void**)&a_hi,   g_a_hi);
    cudaGetSymbolAddress((void**)&a_lo,   g_a_lo);
    cudaGetSymbolAddress((void**)&part,   g_part);

    const size_t PART_S = (size_t)BB * SEQ * DM;

    // 1) fused: gather+bf16 yce, transpose+bf16 P_w, zero-init out region
    prep_fused<<<YCE_BLOCKS + PWT_BLOCKS + ZOUT_BLOCKS, 256>>>(yc, G, Pw, out);
    // 2) py partials (1-term, 4-stage, split-K=2) + xe gather on z=2,3 (256 blocks x 128 rows)
    mma_gemm_kernel<KPY, false, 1, false, 4><<<dim3(DM / 128, (BB * SEQ) / 128, 4), 256, SMEM_NT1>>>(
        yce_hi, yce_hi, 0, KPY,
        pwt_hi, pwt_hi, 0, KPY,
        part, 0, DM, 2, PART_S, 2, x, F);
    // 3) reduce + bias -> py bf16
    reduce_bias_split_py<<<(BB * SEQ * DM) / (256 * 16), 256>>>(Pb);
    // 4) logits (1-term, 4-stage): a[b,s,x] = py[b,s,:] . xe[b,x,:]
    mma_gemm_kernel<DM, false, 1, false, 4><<<dim3(SRC / 128, 1, BB), 256, SMEM_NT1>>>(
        py_hi, py_hi, (size_t)SEQ * DM, DM,
        xe_hi, xe_hi, (size_t)SRC * DM, DM,
        a_out, (size_t)SEQ * SRC, SRC, 1, 0, BB, nullptr, nullptr);
    // 5) masked softmax + split
    softmax_mask_split<<<BB * SEQ, 256>>>(a_out, x);
    // 6) out (3-term, 3-stage, split-K=2 via RED, trans-B): M=128, N=512, K=1024
    mma_gemm_kernel<SRC, true, 3, true, 3><<<dim3(DM / 128, 1, BB * 2), 256, SMEM_TR3>>>(
        a_hi, a_lo, (size_t)SEQ * SRC, SRC,
        xe_hi, xe_lo, (size_t)SRC * DM, DM,
        out, (size_t)SEQ * DM, DM, 2, 0, BB * 2, nullptr, nullptr);
}